// round 13
// baseline (speedup 1.0000x reference)
#include <cuda_runtime.h>
#include <cstdint>

// ALNNLayer fused, single kernel. thread = (k-group {7,6}) x (8 b) x (1 d), 128 thr,
// grid (50, 8) = 400 blocks. Per-l-step weight loads batched (r12 win). Epilogue fused:
// last chunk-block per btile applies bias+relu to its contiguous accum slab.
// Shapes: X,T,M,DT: [B=64, L=200, D=64]; alpha: [K=13]; w_v,b_t: [K,L,D];
//         w_t: [K,L,D,4]; b_v: [K,1,D]; out: [B,K,D].
// Math per (b,k,l,d):
//   kern  = exp(-relu(alpha_k)*|T-4k|) = 2^(-|a*T + na|), a = relu(alpha)*log2e, na = -a*4k
//   inten = kern * relu(X)
//   lat   = relu(wt0*X + wt1*DT + wt2*inten + wt3*M + 4*b_t)
//   out[b,k,d] = relu( sum_l w_v*lat + 200*b_v[k,d] )

#define KREF 13
#define LN   200
#define DN   64
#define BN   64
#define BT   8
#define LC   4
#define NCH  (LN / LC)          // 50
#define NBT  (BN / BT)          // 8
#define BKD  (BN * KREF * DN)   // 53248
#define KT   7                  // max k's per k-group
#define SLAB (BT * KREF * DN)   // 6656 floats per btile slab

// accumulator[b][k][d] — starts zero (static init); fused epilogue re-zeroes it.
__device__ __align__(16) float g_accum[BKD];
// per-btile completion counters — start zero; last block resets.
__device__ int g_count[NBT];

__device__ __forceinline__ float ex2f(float x) {
    float r; asm("ex2.approx.ftz.f32 %0, %1;" : "=f"(r) : "f"(x)); return r;
}

__global__ __launch_bounds__(128, 3)
void alnn_main(const float* __restrict__ X, const float* __restrict__ T,
               const float* __restrict__ M, const float* __restrict__ DT,
               const float* __restrict__ alpha,
               const float* __restrict__ w_v, const float* __restrict__ w_t,
               const float* __restrict__ b_t,
               const float* __restrict__ b_v, float* __restrict__ out)
{
    const int chunk = blockIdx.x;            // 0..49
    const int btile = blockIdx.y;            // 0..7
    const int warp  = threadIdx.x >> 5;      // 0..3
    const int lane  = threadIdx.x & 31;
    const int kg    = warp >> 1;             // 0/1
    const int dg    = warp & 1;              // 0/1
    const int d     = dg * 32 + lane;        // 0..63
    const int kbase = kg ? 7 : 0;
    const int kcnt  = kg ? 6 : 7;
    const int b0    = btile * BT;
    const int l0    = chunk * LC;

    // per-k exp constants
    float a[KT], na[KT];
    #pragma unroll
    for (int kk = 0; kk < KT; kk++) {
        if (kk < kcnt) {
            const int k = kbase + kk;
            const float av = fmaxf(__ldg(alpha + k), 0.0f) * 1.4426950408889634f;
            a[kk]  = av;
            na[kk] = -av * (4.0f * (float)k);
        } else { a[kk] = 0.0f; na[kk] = 0.0f; }
    }

    float acc[KT][BT];
    #pragma unroll
    for (int kk = 0; kk < KT; kk++)
        #pragma unroll
        for (int bi = 0; bi < BT; bi++) acc[kk][bi] = 0.0f;

    const size_t bstr = (size_t)LN * DN;

    #pragma unroll
    for (int li = 0; li < LC; li++) {
        const int l = l0 + li;

        // ---- batch ALL loads for this l-step first (max MLP, one latency hole) ----
        float  wv[KT], bt4[KT];
        float4 wt[KT];
        #pragma unroll
        for (int kk = 0; kk < KT; kk++) {
            if (kk < kcnt) {
                const size_t woff = ((size_t)(kbase + kk) * LN + l) * DN + d;
                wv[kk]  = __ldg(w_v + woff);
                bt4[kk] = __ldg(b_t + woff);
                wt[kk]  = __ldg(reinterpret_cast<const float4*>(w_t) + woff);
            }
        }

        const size_t ibase = (size_t)l * DN + d + (size_t)b0 * bstr;
        float x[BT], t[BT], m[BT], dt[BT], rx[BT];
        #pragma unroll
        for (int bi = 0; bi < BT; bi++) {
            const size_t o = ibase + (size_t)bi * bstr;
            x[bi]  = __ldg(X  + o);
            t[bi]  = __ldg(T  + o);
            m[bi]  = __ldg(M  + o);
            dt[bi] = __ldg(DT + o);
        }

        #pragma unroll
        for (int bi = 0; bi < BT; bi++) rx[bi] = fmaxf(x[bi], 0.0f);
        #pragma unroll
        for (int kk = 0; kk < KT; kk++)
            if (kk < kcnt) bt4[kk] *= 4.0f;

        // ---- compute ----
        #pragma unroll
        for (int kk = 0; kk < KT; kk++) {
            if (kk < kcnt) {
                const float ak = a[kk], nak = na[kk];
                const float4 w = wt[kk];
                const float wvk = wv[kk], btk = bt4[kk];

                #pragma unroll
                for (int bi = 0; bi < BT; bi++) {
                    const float ww = fmaf(t[bi], ak, nak);
                    const float e  = ex2f(-fabsf(ww));       // 2^(-|w|)
                    const float in = e * rx[bi];
                    const float s  = fmaf(w.x, x[bi],
                                     fmaf(w.y, dt[bi],
                                     fmaf(w.z, in,
                                     fmaf(w.w, m[bi], btk))));
                    acc[kk][bi] = fmaf(wvk, fmaxf(s, 0.0f), acc[kk][bi]);
                }
            }
        }
    }

    // coalesced fp32 reductions into the L2-resident accumulator
    #pragma unroll
    for (int kk = 0; kk < KT; kk++) {
        if (kk < kcnt) {
            #pragma unroll
            for (int bi = 0; bi < BT; bi++) {
                atomicAdd(&g_accum[((size_t)(b0 + bi) * KREF + (kbase + kk)) * DN + d],
                          acc[kk][bi]);
            }
        }
    }

    // ---- fused epilogue: last chunk-block of this btile applies bias+relu ----
    __threadfence();                         // make our atomics globally visible
    __syncthreads();                         // all threads' atomics issued

    __shared__ int s_last;
    if (threadIdx.x == 0)
        s_last = (atomicAdd(&g_count[btile], 1) == NCH - 1);
    __syncthreads();

    if (s_last) {
        // slab for b in [b0, b0+8): contiguous floats [b0*KREF*DN, ...+SLAB)
        const int base = b0 * (KREF * DN);
        for (int i = threadIdx.x; i < SLAB / 4; i += 128) {
            const int idx = base + i * 4;          // global accum index (float)
            const int k   = (idx >> 6) % KREF;
            const int dql = idx & 63;
            float4* ap = reinterpret_cast<float4*>(g_accum + idx);
            const float4 s  = *ap;
            const float4 bv = *reinterpret_cast<const float4*>(b_v + k * DN + dql);
            float4 o;
            o.x = fmaxf(fmaf(200.f, bv.x, s.x), 0.f);
            o.y = fmaxf(fmaf(200.f, bv.y, s.y), 0.f);
            o.z = fmaxf(fmaf(200.f, bv.z, s.z), 0.f);
            o.w = fmaxf(fmaf(200.f, bv.w, s.w), 0.f);
            *reinterpret_cast<float4*>(out + idx) = o;
            *ap = make_float4(0.f, 0.f, 0.f, 0.f);    // re-zero for next replay
        }
        __syncthreads();
        if (threadIdx.x == 0) g_count[btile] = 0;     // reset counter for next replay
    }
}

extern "C" void kernel_launch(void* const* d_in, const int* in_sizes, int n_in,
                              void* d_out, int out_size)
{
    // metadata order: X, T, M, DT, alpha, w_v, w_t, b_v, b_t
    const float* X     = (const float*)d_in[0];
    const float* T     = (const float*)d_in[1];
    const float* M     = (const float*)d_in[2];
    const float* DT    = (const float*)d_in[3];
    const float* alpha = (const float*)d_in[4];
    const float* w_v   = (const float*)d_in[5];
    const float* w_t   = (const float*)d_in[6];
    const float* b_v   = (const float*)d_in[7];
    const float* b_t   = (const float*)d_in[8];
    float* out = (float*)d_out;

    dim3 grid(NCH, NBT);
    alnn_main<<<grid, 128>>>(X, T, M, DT, alpha, w_v, w_t, b_t, b_v, out);
}

// round 14
// speedup vs baseline: 1.0805x; 1.0805x over previous
#include <cuda_runtime.h>
#include <cstdint>

// ALNNLayer fused. Block = 64 thr (2 d-split warps); k-groups {4,3,3,3} split across
// grid.z; thread = (4|3 k) x (8 b) x (1 d). All per-l-step loads batched (r12 win).
// 8 blocks/SM (16 warps/SM). L-reduction via coalesced fp32 atomicAdd into a 213KB
// L2-resident accumulator; separate bias+relu epilogue (r12-proven).
// Shapes: X,T,M,DT: [B=64, L=200, D=64]; alpha: [K=13]; w_v,b_t: [K,L,D];
//         w_t: [K,L,D,4]; b_v: [K,1,D]; out: [B,K,D].
// Math per (b,k,l,d):
//   kern  = exp(-relu(alpha_k)*|T-4k|) = 2^(-|a*T + na|), a = relu(alpha)*log2e, na = -a*4k
//   inten = kern * relu(X)
//   lat   = relu(wt0*X + wt1*DT + wt2*inten + wt3*M + 4*b_t)
//   out[b,k,d] = relu( sum_l w_v*lat + 200*b_v[k,d] )

#define KREF 13
#define LN   200
#define DN   64
#define BN   64
#define BT   8
#define LC   2
#define NCH  (LN / LC)          // 100
#define NBT  (BN / BT)          // 8
#define NKG  4
#define BKD  (BN * KREF * DN)   // 53248
#define KT   4                  // max k's per k-group

// accumulator[b][k][d] — starts zero (static init); biaszero re-zeroes after reading.
__device__ __align__(16) float g_accum[BKD];

__device__ __forceinline__ float ex2f(float x) {
    float r; asm("ex2.approx.ftz.f32 %0, %1;" : "=f"(r) : "f"(x)); return r;
}

__global__ __launch_bounds__(64, 8)
void alnn_main(const float* __restrict__ X, const float* __restrict__ T,
               const float* __restrict__ M, const float* __restrict__ DT,
               const float* __restrict__ alpha,
               const float* __restrict__ w_v, const float* __restrict__ w_t,
               const float* __restrict__ b_t)
{
    const int chunk = blockIdx.x;            // 0..99
    const int btile = blockIdx.y;            // 0..7
    const int kgi   = blockIdx.z;            // 0..3
    const int d     = threadIdx.x;           // 0..63 (2 warps, d-split)
    const int kbase = kgi ? (3 * kgi + 1) : 0;   // 0,4,7,10
    const int kcnt  = kgi ? 3 : 4;               // 4,3,3,3
    const int b0    = btile * BT;
    const int l0    = chunk * LC;

    // per-k exp constants
    float a[KT], na[KT];
    #pragma unroll
    for (int kk = 0; kk < KT; kk++) {
        if (kk < kcnt) {
            const int k = kbase + kk;
            const float av = fmaxf(__ldg(alpha + k), 0.0f) * 1.4426950408889634f;
            a[kk]  = av;
            na[kk] = -av * (4.0f * (float)k);
        } else { a[kk] = 0.0f; na[kk] = 0.0f; }
    }

    float acc[KT][BT];
    #pragma unroll
    for (int kk = 0; kk < KT; kk++)
        #pragma unroll
        for (int bi = 0; bi < BT; bi++) acc[kk][bi] = 0.0f;

    const size_t bstr = (size_t)LN * DN;

    #pragma unroll
    for (int li = 0; li < LC; li++) {
        const int l = l0 + li;

        // ---- batch ALL loads for this l-step first (max MLP, one latency hole) ----
        float  wv[KT], bt4[KT];
        float4 wt[KT];
        #pragma unroll
        for (int kk = 0; kk < KT; kk++) {
            if (kk < kcnt) {
                const size_t woff = ((size_t)(kbase + kk) * LN + l) * DN + d;
                wv[kk]  = __ldg(w_v + woff);
                bt4[kk] = __ldg(b_t + woff);
                wt[kk]  = __ldg(reinterpret_cast<const float4*>(w_t) + woff);
            }
        }

        const size_t ibase = (size_t)l * DN + d + (size_t)b0 * bstr;
        float x[BT], t[BT], m[BT], dt[BT], rx[BT];
        #pragma unroll
        for (int bi = 0; bi < BT; bi++) {
            const size_t o = ibase + (size_t)bi * bstr;
            x[bi]  = __ldg(X  + o);
            t[bi]  = __ldg(T  + o);
            m[bi]  = __ldg(M  + o);
            dt[bi] = __ldg(DT + o);
        }

        #pragma unroll
        for (int bi = 0; bi < BT; bi++) rx[bi] = fmaxf(x[bi], 0.0f);
        #pragma unroll
        for (int kk = 0; kk < KT; kk++)
            if (kk < kcnt) bt4[kk] *= 4.0f;

        // ---- compute ----
        #pragma unroll
        for (int kk = 0; kk < KT; kk++) {
            if (kk < kcnt) {
                const float ak = a[kk], nak = na[kk];
                const float4 w = wt[kk];
                const float wvk = wv[kk], btk = bt4[kk];

                #pragma unroll
                for (int bi = 0; bi < BT; bi++) {
                    const float ww = fmaf(t[bi], ak, nak);
                    const float e  = ex2f(-fabsf(ww));       // 2^(-|w|)
                    const float in = e * rx[bi];
                    const float s  = fmaf(w.x, x[bi],
                                     fmaf(w.y, dt[bi],
                                     fmaf(w.z, in,
                                     fmaf(w.w, m[bi], btk))));
                    acc[kk][bi] = fmaf(wvk, fmaxf(s, 0.0f), acc[kk][bi]);
                }
            }
        }
    }

    // coalesced fp32 reductions into the L2-resident accumulator
    #pragma unroll
    for (int kk = 0; kk < KT; kk++) {
        if (kk < kcnt) {
            #pragma unroll
            for (int bi = 0; bi < BT; bi++) {
                atomicAdd(&g_accum[((size_t)(b0 + bi) * KREF + (kbase + kk)) * DN + d],
                          acc[kk][bi]);
            }
        }
    }
}

// bias + relu epilogue; one scalar per thread (208 blocks). Re-zeroes accumulator.
__global__ __launch_bounds__(256)
void alnn_biaszero(const float* __restrict__ b_v, float* __restrict__ out)
{
    const int g = blockIdx.x * 256 + threadIdx.x;   // over BKD = 53248
    if (g >= BKD) return;
    const int d  = g & 63;
    const int k  = (g >> 6) % KREF;

    const float s  = g_accum[g];
    const float bv = __ldg(b_v + k * DN + d);
    out[g] = fmaxf(fmaf(200.f, bv, s), 0.f);
    g_accum[g] = 0.f;                               // ready for next call
}

extern "C" void kernel_launch(void* const* d_in, const int* in_sizes, int n_in,
                              void* d_out, int out_size)
{
    // metadata order: X, T, M, DT, alpha, w_v, w_t, b_v, b_t
    const float* X     = (const float*)d_in[0];
    const float* T     = (const float*)d_in[1];
    const float* M     = (const float*)d_in[2];
    const float* DT    = (const float*)d_in[3];
    const float* alpha = (const float*)d_in[4];
    const float* w_v   = (const float*)d_in[5];
    const float* w_t   = (const float*)d_in[6];
    const float* b_v   = (const float*)d_in[7];
    const float* b_t   = (const float*)d_in[8];
    float* out = (float*)d_out;

    dim3 grid(NCH, NBT, NKG);
    alnn_main<<<grid, 64>>>(X, T, M, DT, alpha, w_v, w_t, b_t);
    alnn_biaszero<<<(BKD + 255) / 256, 256>>>(b_v, out);
}